// round 1
// baseline (speedup 1.0000x reference)
#include <cuda_runtime.h>
#include <math.h>

// ---------------- device globals (no allocation allowed) ----------------
__device__ unsigned long long g_Kpk[64 * 32]; // K[s][m] duplicated as packed {k,k}
__device__ float g_c[64];                     // c[s] = x_pred[s] - sum_m K[s][m]*hx[m]

// ---------------- packed f32x2 helpers ----------------
__device__ __forceinline__ unsigned long long pk2(float lo, float hi) {
    unsigned long long r;
    asm("mov.b64 %0, {%1, %2};" : "=l"(r) : "f"(lo), "f"(hi));
    return r;
}
__device__ __forceinline__ float2 unpk2(unsigned long long v) {
    float2 r;
    asm("mov.b64 {%0, %1}, %2;" : "=f"(r.x), "=f"(r.y) : "l"(v));
    return r;
}
__device__ __forceinline__ void ffma2(unsigned long long& d, unsigned long long a,
                                      unsigned long long b) {
    asm("fma.rn.f32x2 %0, %1, %2, %0;" : "+l"(d) : "l"(a), "l"(b));
}

// ---------------- setup: compute K (packed) and c, one block ----------------
// dynamic smem layout (floats):
//   [0      .. 4095 ] sF  (F)            -> later reused: aug[32][66] at [0..2111]
//   [4096   .. 8191 ] sB  (P -> Pp -> K)
//   [8192   ..12287 ] sC  (T -> PHt[0..2047] + H copy[2048..4095])
__global__ void akf_setup(const float* __restrict__ F, const float* __restrict__ H,
                          const float* __restrict__ Q, const float* __restrict__ R,
                          const float* __restrict__ P, const float* __restrict__ x) {
    extern __shared__ float sm[];
    float* sF = sm;
    float* sB = sm + 4096;
    float* sC = sm + 8192;
    __shared__ float xp[64];
    __shared__ float hx[32];
    __shared__ float fct[32];
    __shared__ int s_piv;

    const int tid = threadIdx.x; // 256 threads

    for (int e = tid; e < 4096; e += 256) { sF[e] = F[e]; sB[e] = P[e]; }
    __syncthreads();

    // x_pred = F @ x
    if (tid < 64) {
        float s = 0.f;
        for (int k = 0; k < 64; ++k) s += sF[tid * 64 + k] * x[k];
        xp[tid] = s;
    }

    // T = F @ P  -> sC   (4x4 register tiles, 16x16 thread grid)
    const int tx = tid & 15, ty = tid >> 4;
    const int i0 = ty * 4, j0 = tx * 4;
    {
        float acc[4][4] = {};
        for (int k = 0; k < 64; ++k) {
            float a[4], b[4];
#pragma unroll
            for (int r = 0; r < 4; ++r) a[r] = sF[(i0 + r) * 64 + k];
#pragma unroll
            for (int c = 0; c < 4; ++c) b[c] = sB[k * 64 + j0 + c];
#pragma unroll
            for (int r = 0; r < 4; ++r)
#pragma unroll
                for (int c = 0; c < 4; ++c) acc[r][c] += a[r] * b[c];
        }
#pragma unroll
        for (int r = 0; r < 4; ++r)
#pragma unroll
            for (int c = 0; c < 4; ++c) sC[(i0 + r) * 64 + j0 + c] = acc[r][c];
    }
    __syncthreads();

    // Pp = T @ F^T + Q  -> sB (P dead)
    {
        float acc[4][4] = {};
        for (int k = 0; k < 64; ++k) {
            float a[4], b[4];
#pragma unroll
            for (int r = 0; r < 4; ++r) a[r] = sC[(i0 + r) * 64 + k];
#pragma unroll
            for (int c = 0; c < 4; ++c) b[c] = sF[(j0 + c) * 64 + k];
#pragma unroll
            for (int r = 0; r < 4; ++r)
#pragma unroll
                for (int c = 0; c < 4; ++c) acc[r][c] += a[r] * b[c];
        }
        __syncthreads(); // all reads of sC(T)/sF done before overwrite below
#pragma unroll
        for (int r = 0; r < 4; ++r)
#pragma unroll
            for (int c = 0; c < 4; ++c)
                sB[(i0 + r) * 64 + j0 + c] = acc[r][c] + Q[(i0 + r) * 64 + j0 + c];
    }
    __syncthreads();

    // hx = H @ x_pred ; copy H into sC[2048..4095] (T dead)
    if (tid < 32) {
        float s = 0.f;
        for (int k = 0; k < 64; ++k) s += H[tid * 64 + k] * xp[k];
        hx[tid] = s;
    }
    for (int e = tid; e < 2048; e += 256) sC[2048 + e] = H[e];
    __syncthreads();

    // PHt[i][m] = sum_l Pp[i][l] * H[m][l]  -> sC[0..2047] (layout [64][32])
    for (int e = tid; e < 2048; e += 256) {
        int i = e >> 5, m = e & 31;
        float s = 0.f;
        for (int l = 0; l < 64; ++l) s += sB[i * 64 + l] * sC[2048 + m * 64 + l];
        sC[e] = s;
    }
    __syncthreads();

    // S = H @ PHt + R  -> aug (in sF region; F dead).  aug is 32 x 66, [S | I]
    float* aug = sF;
    for (int e = tid; e < 1024; e += 256) {
        int m = e >> 5, n = e & 31;
        float s = R[m * 32 + n];
        for (int l = 0; l < 64; ++l) s += sC[2048 + m * 64 + l] * sC[l * 32 + n];
        aug[m * 66 + n] = s;
        aug[m * 66 + 32 + n] = (m == n) ? 1.f : 0.f;
    }
    __syncthreads();

    // Gauss-Jordan with partial pivoting: aug -> [I | S^-1]
    for (int col = 0; col < 32; ++col) {
        if (tid == 0) {
            int p = col;
            float best = fabsf(aug[col * 66 + col]);
            for (int r = col + 1; r < 32; ++r) {
                float v = fabsf(aug[r * 66 + col]);
                if (v > best) { best = v; p = r; }
            }
            s_piv = p;
        }
        __syncthreads();
        int p = s_piv;
        if (p != col && tid < 64) {
            float t1 = aug[col * 66 + tid];
            aug[col * 66 + tid] = aug[p * 66 + tid];
            aug[p * 66 + tid] = t1;
        }
        __syncthreads();
        float pvinv = 1.0f / aug[col * 66 + col];
        __syncthreads();
        if (tid < 64) aug[col * 66 + tid] *= pvinv;
        if (tid < 32) fct[tid] = aug[tid * 66 + col]; // rows != col unaffected by normalize
        __syncthreads();
        for (int e = tid; e < 2048; e += 256) {
            int r = e >> 6, t1 = e & 63;
            if (r != col) aug[r * 66 + t1] -= fct[r] * aug[col * 66 + t1];
        }
        __syncthreads();
    }

    // K = PHt @ Sinv   (Sinv[l][m] = aug[l*66+32+m]);  store packed + plain (for c)
    for (int e = tid; e < 2048; e += 256) {
        int s = e >> 5, m = e & 31;
        float acc = 0.f;
        for (int l = 0; l < 32; ++l) acc += sC[s * 32 + l] * aug[l * 66 + 32 + m];
        g_Kpk[e] = pk2(acc, acc);
        sB[e] = acc; // plain K for c computation (Pp dead)
    }
    __syncthreads();

    // c = x_pred - K @ hx
    if (tid < 64) {
        float s1 = xp[tid];
        for (int m = 0; m < 32; ++m) s1 -= sB[tid * 32 + m] * hx[m];
        g_c[tid] = s1;
    }
}

// ---------------- main: out[:, j] = c + K @ z[:, j], 4 columns/thread ----------------
__global__ __launch_bounds__(256) void akf_main(const float* __restrict__ z,
                                                float* __restrict__ out, int N) {
    __shared__ unsigned long long sK[64 * 32];
    __shared__ float sc[64];
    const int tid = threadIdx.x;
    for (int e = tid; e < 2048; e += 256) sK[e] = g_Kpk[e];
    if (tid < 64) sc[tid] = g_c[tid];
    __syncthreads();

    const int nq = N >> 2;
    const int t = blockIdx.x * 256 + tid; // float4-column index
    if (t >= nq) return;

    const float4* __restrict__ z4 = (const float4*)z;
    float4* __restrict__ out4 = (float4*)out;

    // load this thread's 4 z columns (32 rows), pack into f32x2 pairs
    unsigned long long za[32], zb[32];
#pragma unroll
    for (int m = 0; m < 32; ++m) {
        float4 v = z4[m * nq + t];
        za[m] = pk2(v.x, v.y);
        zb[m] = pk2(v.z, v.w);
    }

#pragma unroll 1
    for (int ch = 0; ch < 8; ++ch) {
        const int s0 = ch * 8;
        unsigned long long accA[8], accB[8];
#pragma unroll
        for (int i = 0; i < 8; ++i) {
            float cv = sc[s0 + i];
            unsigned long long cp = pk2(cv, cv);
            accA[i] = cp;
            accB[i] = cp;
        }
#pragma unroll
        for (int m = 0; m < 32; ++m) {
#pragma unroll
            for (int i = 0; i < 8; ++i) {
                unsigned long long kk = sK[(s0 + i) * 32 + m];
                ffma2(accA[i], kk, za[m]);
                ffma2(accB[i], kk, zb[m]);
            }
        }
#pragma unroll
        for (int i = 0; i < 8; ++i) {
            float2 a = unpk2(accA[i]);
            float2 b = unpk2(accB[i]);
            out4[(s0 + i) * nq + t] = make_float4(a.x, a.y, b.x, b.y);
        }
    }
}

// ---------------- fallback for N % 4 != 0 (scalar, one column/thread) ----------------
__global__ void akf_simple(const float* __restrict__ z, float* __restrict__ out, int N) {
    __shared__ float sK[64 * 32];
    __shared__ float sc[64];
    const int tid = threadIdx.x;
    for (int e = tid; e < 2048; e += 256) sK[e] = unpk2(g_Kpk[e]).x;
    if (tid < 64) sc[tid] = g_c[tid];
    __syncthreads();
    int j = blockIdx.x * 256 + tid;
    if (j >= N) return;
    float zc[32];
#pragma unroll
    for (int m = 0; m < 32; ++m) zc[m] = z[m * N + j];
#pragma unroll 1
    for (int s = 0; s < 64; ++s) {
        float acc = sc[s];
#pragma unroll
        for (int m = 0; m < 32; ++m) acc += sK[s * 32 + m] * zc[m];
        out[s * N + j] = acc;
    }
}

extern "C" void kernel_launch(void* const* d_in, const int* in_sizes, int n_in,
                              void* d_out, int out_size) {
    const float* z = (const float*)d_in[0];
    const float* F = (const float*)d_in[1];
    const float* H = (const float*)d_in[2];
    const float* Q = (const float*)d_in[3];
    const float* R = (const float*)d_in[4];
    const float* P = (const float*)d_in[5];
    const float* x = (const float*)d_in[6];
    const int N = in_sizes[0] / 32;

    cudaFuncSetAttribute(akf_setup, cudaFuncAttributeMaxDynamicSharedMemorySize, 49152);
    akf_setup<<<1, 256, 49152>>>(F, H, Q, R, P, x);

    if ((N & 3) == 0) {
        int nq = N >> 2;
        int blocks = (nq + 255) / 256;
        akf_main<<<blocks, 256>>>(z, (float*)d_out, N);
    } else {
        akf_simple<<<(N + 255) / 256, 256>>>(z, (float*)d_out, N);
    }
}

// round 3
// speedup vs baseline: 1.5355x; 1.5355x over previous
#include <cuda_runtime.h>
#include <math.h>

// ---------------- device globals (no allocation allowed) ----------------
__device__ unsigned long long g_Kpk[64 * 32]; // K[s][m] duplicated as packed {k,k}
__device__ float g_c[64];                     // c[s] = x_pred[s] - sum_m K[s][m]*hx[m]

// ---------------- packed f32x2 helpers ----------------
__device__ __forceinline__ unsigned long long pk2(float lo, float hi) {
    unsigned long long r;
    asm("mov.b64 %0, {%1, %2};" : "=l"(r) : "f"(lo), "f"(hi));
    return r;
}
__device__ __forceinline__ float2 unpk2(unsigned long long v) {
    float2 r;
    asm("mov.b64 {%0, %1}, %2;" : "=f"(r.x), "=f"(r.y) : "l"(v));
    return r;
}
__device__ __forceinline__ void ffma2(unsigned long long& d, unsigned long long a,
                                      unsigned long long b) {
    asm("fma.rn.f32x2 %0, %1, %2, %0;" : "+l"(d) : "l"(a), "l"(b));
}

// ---------------- setup: compute K (packed) and c, one block ----------------
// dynamic smem layout (floats):
//   [0      .. 4095 ] sF  (F)            -> later reused: aug[32][66] at [0..2111]
//   [4096   .. 8191 ] sB  (P -> Pp -> K)
//   [8192   ..12287 ] sC  (T -> PHt[0..2047] + H copy[2048..4095])
__global__ void akf_setup(const float* __restrict__ F, const float* __restrict__ H,
                          const float* __restrict__ Q, const float* __restrict__ R,
                          const float* __restrict__ P, const float* __restrict__ x) {
    extern __shared__ float sm[];
    float* sF = sm;
    float* sB = sm + 4096;
    float* sC = sm + 8192;
    __shared__ float xp[64];
    __shared__ float hx[32];
    __shared__ float fct[32];
    __shared__ int s_piv;

    const int tid = threadIdx.x; // 256 threads

    for (int e = tid; e < 4096; e += 256) { sF[e] = F[e]; sB[e] = P[e]; }
    __syncthreads();

    // x_pred = F @ x
    if (tid < 64) {
        float s = 0.f;
        for (int k = 0; k < 64; ++k) s += sF[tid * 64 + k] * x[k];
        xp[tid] = s;
    }

    // T = F @ P  -> sC   (4x4 register tiles, 16x16 thread grid)
    const int tx = tid & 15, ty = tid >> 4;
    const int i0 = ty * 4, j0 = tx * 4;
    {
        float acc[4][4] = {};
        for (int k = 0; k < 64; ++k) {
            float a[4], b[4];
#pragma unroll
            for (int r = 0; r < 4; ++r) a[r] = sF[(i0 + r) * 64 + k];
#pragma unroll
            for (int c = 0; c < 4; ++c) b[c] = sB[k * 64 + j0 + c];
#pragma unroll
            for (int r = 0; r < 4; ++r)
#pragma unroll
                for (int c = 0; c < 4; ++c) acc[r][c] += a[r] * b[c];
        }
#pragma unroll
        for (int r = 0; r < 4; ++r)
#pragma unroll
            for (int c = 0; c < 4; ++c) sC[(i0 + r) * 64 + j0 + c] = acc[r][c];
    }
    __syncthreads();

    // Pp = T @ F^T + Q  -> sB (P dead)
    {
        float acc[4][4] = {};
        for (int k = 0; k < 64; ++k) {
            float a[4], b[4];
#pragma unroll
            for (int r = 0; r < 4; ++r) a[r] = sC[(i0 + r) * 64 + k];
#pragma unroll
            for (int c = 0; c < 4; ++c) b[c] = sF[(j0 + c) * 64 + k];
#pragma unroll
            for (int r = 0; r < 4; ++r)
#pragma unroll
                for (int c = 0; c < 4; ++c) acc[r][c] += a[r] * b[c];
        }
        __syncthreads(); // all reads of sC(T)/sF done before overwrite below
#pragma unroll
        for (int r = 0; r < 4; ++r)
#pragma unroll
            for (int c = 0; c < 4; ++c)
                sB[(i0 + r) * 64 + j0 + c] = acc[r][c] + Q[(i0 + r) * 64 + j0 + c];
    }
    __syncthreads();

    // hx = H @ x_pred ; copy H into sC[2048..4095] (T dead)
    if (tid < 32) {
        float s = 0.f;
        for (int k = 0; k < 64; ++k) s += H[tid * 64 + k] * xp[k];
        hx[tid] = s;
    }
    for (int e = tid; e < 2048; e += 256) sC[2048 + e] = H[e];
    __syncthreads();

    // PHt[i][m] = sum_l Pp[i][l] * H[m][l]  -> sC[0..2047] (layout [64][32])
    for (int e = tid; e < 2048; e += 256) {
        int i = e >> 5, m = e & 31;
        float s = 0.f;
        for (int l = 0; l < 64; ++l) s += sB[i * 64 + l] * sC[2048 + m * 64 + l];
        sC[e] = s;
    }
    __syncthreads();

    // S = H @ PHt + R  -> aug (in sF region; F dead).  aug is 32 x 66, [S | I]
    float* aug = sF;
    for (int e = tid; e < 1024; e += 256) {
        int m = e >> 5, n = e & 31;
        float s = R[m * 32 + n];
        for (int l = 0; l < 64; ++l) s += sC[2048 + m * 64 + l] * sC[l * 32 + n];
        aug[m * 66 + n] = s;
        aug[m * 66 + 32 + n] = (m == n) ? 1.f : 0.f;
    }
    __syncthreads();

    // Gauss-Jordan with partial pivoting: aug -> [I | S^-1]
    for (int col = 0; col < 32; ++col) {
        if (tid == 0) {
            int p = col;
            float best = fabsf(aug[col * 66 + col]);
            for (int r = col + 1; r < 32; ++r) {
                float v = fabsf(aug[r * 66 + col]);
                if (v > best) { best = v; p = r; }
            }
            s_piv = p;
        }
        __syncthreads();
        int p = s_piv;
        if (p != col && tid < 64) {
            float t1 = aug[col * 66 + tid];
            aug[col * 66 + tid] = aug[p * 66 + tid];
            aug[p * 66 + tid] = t1;
        }
        __syncthreads();
        float pvinv = 1.0f / aug[col * 66 + col];
        __syncthreads();
        if (tid < 64) aug[col * 66 + tid] *= pvinv;
        if (tid < 32) fct[tid] = aug[tid * 66 + col]; // rows != col unaffected by normalize
        __syncthreads();
        for (int e = tid; e < 2048; e += 256) {
            int r = e >> 6, t1 = e & 63;
            if (r != col) aug[r * 66 + t1] -= fct[r] * aug[col * 66 + t1];
        }
        __syncthreads();
    }

    // K = PHt @ Sinv   (Sinv[l][m] = aug[l*66+32+m]);  store packed + plain (for c)
    for (int e = tid; e < 2048; e += 256) {
        int s = e >> 5, m = e & 31;
        float acc = 0.f;
        for (int l = 0; l < 32; ++l) acc += sC[s * 32 + l] * aug[l * 66 + 32 + m];
        g_Kpk[e] = pk2(acc, acc);
        sB[e] = acc; // plain K for c computation (Pp dead)
    }
    __syncthreads();

    // c = x_pred - K @ hx
    if (tid < 64) {
        float s1 = xp[tid];
        for (int m = 0; m < 32; ++m) s1 -= sB[tid * 32 + m] * hx[m];
        g_c[tid] = s1;
    }
}

// ---------------- main: out[:, j] = c + K @ z[:, j], 4 columns/thread ----------------
__global__ __launch_bounds__(256) void akf_main(const float* __restrict__ z,
                                                float* __restrict__ out, int N) {
    __shared__ unsigned long long sK[64 * 32];
    __shared__ float sc[64];
    const int tid = threadIdx.x;
    for (int e = tid; e < 2048; e += 256) sK[e] = g_Kpk[e];
    if (tid < 64) sc[tid] = g_c[tid];
    __syncthreads();

    const int nq = N >> 2;
    const int t = blockIdx.x * 256 + tid; // float4-column index
    if (t >= nq) return;

    const float4* __restrict__ z4 = (const float4*)z;
    float4* __restrict__ out4 = (float4*)out;

    // load this thread's 4 z columns (32 rows), pack into f32x2 pairs
    unsigned long long za[32], zb[32];
#pragma unroll
    for (int m = 0; m < 32; ++m) {
        float4 v = z4[m * nq + t];
        za[m] = pk2(v.x, v.y);
        zb[m] = pk2(v.z, v.w);
    }

#pragma unroll 1
    for (int ch = 0; ch < 8; ++ch) {
        const int s0 = ch * 8;
        unsigned long long accA[8], accB[8];
#pragma unroll
        for (int i = 0; i < 8; ++i) {
            float cv = sc[s0 + i];
            unsigned long long cp = pk2(cv, cv);
            accA[i] = cp;
            accB[i] = cp;
        }
#pragma unroll
        for (int m = 0; m < 32; ++m) {
#pragma unroll
            for (int i = 0; i < 8; ++i) {
                unsigned long long kk = sK[(s0 + i) * 32 + m];
                ffma2(accA[i], kk, za[m]);
                ffma2(accB[i], kk, zb[m]);
            }
        }
#pragma unroll
        for (int i = 0; i < 8; ++i) {
            float2 a = unpk2(accA[i]);
            float2 b = unpk2(accB[i]);
            out4[(s0 + i) * nq + t] = make_float4(a.x, a.y, b.x, b.y);
        }
    }
}

// ---------------- fallback for N % 4 != 0 (scalar, one column/thread) ----------------
__global__ void akf_simple(const float* __restrict__ z, float* __restrict__ out, int N) {
    __shared__ float sK[64 * 32];
    __shared__ float sc[64];
    const int tid = threadIdx.x;
    for (int e = tid; e < 2048; e += 256) sK[e] = unpk2(g_Kpk[e]).x;
    if (tid < 64) sc[tid] = g_c[tid];
    __syncthreads();
    int j = blockIdx.x * 256 + tid;
    if (j >= N) return;
    float zc[32];
#pragma unroll
    for (int m = 0; m < 32; ++m) zc[m] = z[m * N + j];
#pragma unroll 1
    for (int s = 0; s < 64; ++s) {
        float acc = sc[s];
#pragma unroll
        for (int m = 0; m < 32; ++m) acc += sK[s * 32 + m] * zc[m];
        out[s * N + j] = acc;
    }
}

extern "C" void kernel_launch(void* const* d_in, const int* in_sizes, int n_in,
                              void* d_out, int out_size) {
    const float* z = (const float*)d_in[0];
    const float* F = (const float*)d_in[1];
    const float* H = (const float*)d_in[2];
    const float* Q = (const float*)d_in[3];
    const float* R = (const float*)d_in[4];
    const float* P = (const float*)d_in[5];
    const float* x = (const float*)d_in[6];
    const int N = in_sizes[0] / 32;

    cudaFuncSetAttribute(akf_setup, cudaFuncAttributeMaxDynamicSharedMemorySize, 49152);
    akf_setup<<<1, 256, 49152>>>(F, H, Q, R, P, x);

    if ((N & 3) == 0) {
        int nq = N >> 2;
        int blocks = (nq + 255) / 256;
        akf_main<<<blocks, 256>>>(z, (float*)d_out, N);
    } else {
        akf_simple<<<(N + 255) / 256, 256>>>(z, (float*)d_out, N);
    }
}